// round 17
// baseline (speedup 1.0000x reference)
#include <cuda_runtime.h>

// Problem constants (fixed by the reference)
#define N_SAE  128
#define D_DATA 128
#define D_DICT 512
#define BATCH  1024
#define TB     32     // tokens per MMA batch
#define TCAP   48     // max tokens per expert (mean 16; 8-sigma margin)

typedef unsigned long long u64;
typedef unsigned int u32;

// Cross-CTA combine state (MONOTONIC across graph replays; never reset).
// 4 contributions per token per replay: (expert-rank j in {0,1}) x (half h).
// Slot = j*2 + h is identity-keyed -> fixed summation order -> deterministic.
__device__ float g_stage4[BATCH * 4 * D_DATA];   // 2 MB
__device__ int   g_arr  [BATCH];
__device__ int   g_ready[BATCH];

// ---------------- helpers ----------------
__device__ __forceinline__ u64 pk(float lo, float hi) {
    u64 r; asm("mov.b64 %0,{%1,%2};" : "=l"(r) : "f"(lo), "f"(hi)); return r;
}
__device__ __forceinline__ void upk(float& lo, float& hi, u64 v) {
    asm("mov.b64 {%0,%1},%2;" : "=f"(lo), "=f"(hi) : "l"(v));
}
__device__ __forceinline__ u64 add2(u64 a, u64 b) {
    u64 d; asm("add.rn.f32x2 %0,%1,%2;" : "=l"(d) : "l"(a), "l"(b)); return d;
}
__device__ __forceinline__ u32 tf32r(float f) {   // unbiased round-to-nearest tf32
    u32 r; asm("cvt.rna.tf32.f32 %0,%1;" : "=r"(r) : "f"(f)); return r;
}
__device__ __forceinline__ void mma_tf32(float& c0, float& c1, float& c2, float& c3,
                                         u32 a0, u32 a1, u32 a2, u32 a3,
                                         u32 b0, u32 b1) {
    asm("mma.sync.aligned.m16n8k8.row.col.f32.tf32.tf32.f32 "
        "{%0,%1,%2,%3},{%4,%5,%6,%7},{%8,%9},{%0,%1,%2,%3};"
        : "+f"(c0), "+f"(c1), "+f"(c2), "+f"(c3)
        : "r"(a0), "r"(a1), "r"(a2), "r"(a3), "r"(b0), "r"(b1));
}
__device__ __forceinline__ u32 smem_u32(const void* p) {
    u32 a;
    asm("{.reg .u64 t; cvta.to.shared.u64 t,%1; cvt.u32.u64 %0,t;}" : "=r"(a) : "l"(p));
    return a;
}
#define CP16(dst, src) \
    asm volatile("cp.async.ca.shared.global [%0],[%1],16;" :: "r"(dst), "l"(src))
#define CP_COMMIT() asm volatile("cp.async.commit_group;" ::: "memory")
#define CP_WAIT2()  asm volatile("cp.async.wait_group 2;" ::: "memory")

// Dynamic smem (floats), per half-expert CTA (<= 113 KB for 2 CTAs/SM):
//  wstg : 16 warps x 4 stages x 8 rows x 24 floats (private rings,
//         same 192-float slice geometry for encode AND decode)      49152 B
//         part u64[2][16][128] (32 KB) ALIASES this region late.
//  xs   : [128][40]                                                 20480 B
//  acts : [256][40] (this half's 256 dict units)                    40960 B
#define WSLOT (4 * 8 * 24)                   // 768 floats per warp ring
#define OFF_WSTG 0
#define OFF_XS   (16 * WSLOT)                // 12288
#define OFF_ACTS (OFF_XS + D_DATA * 40)      // 17408
#define SMEM_FLOATS (OFF_ACTS + 256 * 40)    // 27648
#define SMEM_BYTES  (SMEM_FLOATS * 4)        // 110592 B

// ---------------------------------------------------------------------------
// Half-expert CTA: grid = (128 experts, 2 halves), 512 threads (16 warps),
// 2 CTAs/SM. Encode its 256 dict units, decode their contribution, publish
// to identity slot, last arriver per token combines all 4 slots.
// ---------------------------------------------------------------------------
__global__ void __launch_bounds__(512, 2)
k_compute(const float* __restrict__ x,
          const float* __restrict__ gate,
          const float* __restrict__ Wenc,
          const float* __restrict__ Wdec,
          const float* __restrict__ benc,
          const float* __restrict__ bdec,
          float* __restrict__ out) {
    int s = blockIdx.x;
    int h = blockIdx.y;                    // dict half: e in [256h, 256h+256)

    extern __shared__ __align__(16) float smf[];
    float* xs   = smf + OFF_XS;
    float* acts = smf + OFF_ACTS;          // local e' = e - 256h
    u64*   part = (u64*)(smf + OFF_WSTG);  // aliases rings (late epilogue only)

    __shared__ float gsf[64];
    __shared__ int prtok[64];
    __shared__ int pj[64];                 // expert-rank j in {0,1} per token
    __shared__ int sarr[TB];
    __shared__ unsigned masks[32];
    __shared__ int pcnt[32];
    __shared__ int ntot;

    int tid  = threadIdx.x;
    int warp = tid >> 5, lane = tid & 31;
    int g = lane >> 2, t = lane & 3;       // mma fragment coords

    float* wreg = smf + OFF_WSTG + warp * WSLOT;
    u32 wregu = smem_u32(wreg);

    const float* WencS = Wenc + (size_t)s * D_DATA * D_DICT;
    const float* WdecS = Wdec + (size_t)s * D_DICT * D_DATA;

    // ---- Routing: column scan of gate[:, s] (proven; identical in both halves) ----
    float v0 = __ldg(&gate[(size_t)tid * N_SAE + s]);
    float v1 = __ldg(&gate[(size_t)(tid + 512) * N_SAE + s]);
    unsigned m0 = __ballot_sync(0xffffffffu, v0 != 0.0f);
    unsigned m1 = __ballot_sync(0xffffffffu, v1 != 0.0f);
    if (lane == 0) { masks[warp] = m0; masks[16 + warp] = m1; }
    if (tid < 64) { prtok[tid] = 0; gsf[tid] = 0.0f; pj[tid] = 0; }
    __syncthreads();
    if (warp == 0) {
        int c = __popc(masks[lane]);
        int ex = c;
        #pragma unroll
        for (int o = 1; o < 32; o <<= 1) {
            int tt = __shfl_up_sync(0xffffffffu, ex, o);
            if (lane >= o) ex += tt;
        }
        pcnt[lane] = ex - c;
        if (lane == 31) ntot = ex;
    }
    __syncthreads();
    int n = ntot; if (n > TCAP) n = TCAP;
    if (n == 0) return;

    if (v0 != 0.0f) {
        int r = pcnt[warp] + __popc(m0 & ((1u << lane) - 1));
        if (r < TCAP) { prtok[r] = tid; gsf[r] = v0; }
    }
    if (v1 != 0.0f) {
        int r = pcnt[16 + warp] + __popc(m1 & ((1u << lane) - 1));
        if (r < TCAP) { prtok[r] = tid + 512; gsf[r] = v1; }
    }
    __syncthreads();

    // ---- Expert-rank j per token (proven row-scan): j = #nonzeros with e' < s ----
    for (int tk = warp; tk < n; tk += 16) {
        int b = prtok[tk];
        float4 gv = ((const float4*)gate)[(size_t)b * (N_SAE / 4) + lane];
        int e0 = lane * 4;
        int c = (gv.x != 0.0f && e0     < s) + (gv.y != 0.0f && e0 + 1 < s)
              + (gv.z != 0.0f && e0 + 2 < s) + (gv.w != 0.0f && e0 + 3 < s);
        #pragma unroll
        for (int o = 16; o > 0; o >>= 1) c += __shfl_xor_sync(0xffffffffu, c, o);
        if (lane == 0) pj[tk] = c;         // 0 or 1
    }

    // Stager role: lane = r*4 + c (r = k-row 0..7, c = 16B chunk 0..3)
    int sr = lane >> 2, sc = lane & 3;

    // ================= Batch loop (usually one iteration) =================
    for (int base = 0; base < n; base += TB) {
        int mb = n - base; if (mb > TB) mb = TB;

        int eg = h * 256 + warp * 16;      // encode e-band (global), m16 tile
        // ---- Encode prologue: stage slices 0..2 (4-deep ring, wait 2) ----
        #pragma unroll
        for (int p = 0; p < 3; p++) {
            const float* src = WencS + (size_t)(8 * p + sr) * D_DICT + eg + sc * 4;
            CP16(wregu + ((p & 3) * 192 + sr * 24 + sc * 4) * 4, src);
            CP_COMMIT();
        }

        // ---- xs[d][slot], tf32-rounded (overlaps prefetch) ----
        for (int i = tid; i < D_DATA * TB; i += 512) {
            int j = i & 31, d = i >> 5;
            float v = (j < mb) ? x[(size_t)prtok[base + j] * D_DATA + d] : 0.0f;
            xs[d * 40 + j] = __uint_as_float(tf32r(v));
        }
        __syncthreads();                   // xs visible

        // ---------------- Encode: C[256e x 32tok], warp = one m16 e-tile ----
        float cE[4][4];
        #pragma unroll
        for (int nt = 0; nt < 4; nt++)
            #pragma unroll
            for (int q = 0; q < 4; q++) cE[nt][q] = 0.0f;

        #pragma unroll 4
        for (int ks = 0; ks < 16; ks++) {
            CP_WAIT2();
            if (ks + 3 < 16) {
                int p = ks + 3;
                const float* src = WencS + (size_t)(8 * p + sr) * D_DICT + eg + sc * 4;
                CP16(wregu + ((p & 3) * 192 + sr * 24 + sc * 4) * 4, src);
            }
            CP_COMMIT();                   // one group per step (empty at tail)
            __syncwarp();

            const float* S = wreg + (ks & 3) * 192;
            u32 a0 = tf32r(S[t * 24 + g    ]);
            u32 a1 = tf32r(S[t * 24 + g + 8]);
            u32 a2 = tf32r(S[(t + 4) * 24 + g    ]);
            u32 a3 = tf32r(S[(t + 4) * 24 + g + 8]);
            #pragma unroll
            for (int nt = 0; nt < 4; nt++) {
                u32 b0 = __float_as_uint(xs[(8 * ks + t    ) * 40 + nt * 8 + g]);
                u32 b1 = __float_as_uint(xs[(8 * ks + t + 4) * 40 + nt * 8 + g]);
                mma_tf32(cE[nt][0], cE[nt][1], cE[nt][2], cE[nt][3],
                         a0, a1, a2, a3, b0, b1);
            }
        }

        // bias + relu + gate + tf32-round -> acts[e_local][slot]
        {
            int el = warp * 16 + g;        // local e row (and +8)
            float bg  = benc[(size_t)s * D_DICT + h * 256 + el];
            float bg8 = benc[(size_t)s * D_DICT + h * 256 + el + 8];
            #pragma unroll
            for (int nt = 0; nt < 4; nt++) {
                int sl = nt * 8 + 2 * t;
                float gt0 = gsf[base + sl], gt1 = gsf[base + sl + 1];
                acts[(el    ) * 40 + sl    ] = __uint_as_float(tf32r(fmaxf(cE[nt][0] + bg , 0.f) * gt0));
                acts[(el    ) * 40 + sl + 1] = __uint_as_float(tf32r(fmaxf(cE[nt][1] + bg , 0.f) * gt1));
                acts[(el + 8) * 40 + sl    ] = __uint_as_float(tf32r(fmaxf(cE[nt][2] + bg8, 0.f) * gt0));
                acts[(el + 8) * 40 + sl + 1] = __uint_as_float(tf32r(fmaxf(cE[nt][3] + bg8, 0.f) * gt1));
            }
        }

        // ---- Decode prologue: stage slices 0..2 (same ring, program order) ----
        int d0 = (warp & 7) * 16;          // decode d-tile
        int kh = warp >> 3;                // K-half within this dict half (128 e)
        int ebase = h * 256 + kh * 128;    // global e base for weights
        #pragma unroll
        for (int p = 0; p < 3; p++) {
            const float* src = WdecS + (size_t)(ebase + 8 * p + sr) * D_DATA + d0 + sc * 4;
            CP16(wregu + ((p & 3) * 192 + sr * 24 + sc * 4) * 4, src);
            CP_COMMIT();
        }
        __syncthreads();                   // acts visible to all warps

        // ---------------- Decode: C[128d x 32tok] over this CTA's e-half ----
        float cD[4][4];
        #pragma unroll
        for (int nt = 0; nt < 4; nt++)
            #pragma unroll
            for (int q = 0; q < 4; q++) cD[nt][q] = 0.0f;

        #pragma unroll 4
        for (int ks = 0; ks < 16; ks++) {
            CP_WAIT2();
            if (ks + 3 < 16) {
                int p = ks + 3;
                const float* src = WdecS + (size_t)(ebase + 8 * p + sr) * D_DATA + d0 + sc * 4;
                CP16(wregu + ((p & 3) * 192 + sr * 24 + sc * 4) * 4, src);
            }
            CP_COMMIT();
            __syncwarp();

            const float* S = wreg + (ks & 3) * 192;
            u32 a0 = tf32r(S[t * 24 + g    ]);
            u32 a1 = tf32r(S[t * 24 + g + 8]);
            u32 a2 = tf32r(S[(t + 4) * 24 + g    ]);
            u32 a3 = tf32r(S[(t + 4) * 24 + g + 8]);
            int el = kh * 128 + 8 * ks;    // local acts row base
            #pragma unroll
            for (int nt = 0; nt < 4; nt++) {
                u32 b0 = __float_as_uint(acts[(el + t    ) * 40 + nt * 8 + g]);
                u32 b1 = __float_as_uint(acts[(el + t + 4) * 40 + nt * 8 + g]);
                mma_tf32(cD[nt][0], cD[nt][1], cD[nt][2], cD[nt][3],
                         a0, a1, a2, a3, b0, b1);
            }
        }
        __syncthreads();   // ALL warps done reading rings before part aliases them

        // part[kh][token-pair nt*4+t][d] = pk(tok even, tok odd)
        #pragma unroll
        for (int nt = 0; nt < 4; nt++) {
            part[kh * 2048 + (nt * 4 + t) * 128 + d0 + g    ] = pk(cD[nt][0], cD[nt][1]);
            part[kh * 2048 + (nt * 4 + t) * 128 + d0 + g + 8] = pk(cD[nt][2], cD[nt][3]);
        }
        __syncthreads();

        // ---- Epilogue: reduce 2 K-halves (+ b_dec on h==0), 4-slot combine ----
        {
            int d  = tid & 127;
            int tl = tid >> 7;             // 0..3; token pairs tl+4q
            float bd = (h == 0) ? bdec[(size_t)s * D_DATA + d] : 0.0f;
            float vv[8];
            #pragma unroll
            for (int q = 0; q < 4; q++) {
                int tp = tl + 4 * q;
                u64 sum = add2(part[tp * 128 + d], part[2048 + tp * 128 + d]);
                float lo, hi; upk(lo, hi, sum);
                vv[2 * q] = lo + bd; vv[2 * q + 1] = hi + bd;
            }

            if (tid < TB) sarr[tid] = (tid < mb) ? atomicAdd(&g_arr[prtok[base + tid]], 1) : 0;
            __syncthreads();

            // Phase 1: EVERY contribution publishes to its identity slot.
            #pragma unroll
            for (int q = 0; q < 4; q++) {
                #pragma unroll
                for (int r = 0; r < 2; r++) {
                    int j = 2 * (tl + 4 * q) + r;
                    if (j < mb) {
                        int slot = pj[base + j] * 2 + h;
                        __stcg(&g_stage4[((size_t)prtok[base + j] * 4 + slot) * D_DATA + d],
                               vv[2 * q + r]);
                    }
                }
            }
            __syncthreads();

            if (tid < mb) {
                __threadfence();
                atomicAdd(&g_ready[prtok[base + tid]], 1);
            }
            // Phase 2: last arriver (role 3) spins for all 4 publishes this round.
            if (tid < mb && (sarr[tid] & 3) == 3) {
                int b = prtok[base + tid];
                int want = ((sarr[tid] >> 2) + 1) * 4;
                while (atomicAdd(&g_ready[b], 0) < want) {}
                __threadfence();
            }
            __syncthreads();

            // Phase 3: finisher sums the 4 slots in FIXED order -> deterministic.
            #pragma unroll
            for (int q = 0; q < 4; q++) {
                #pragma unroll
                for (int r = 0; r < 2; r++) {
                    int j = 2 * (tl + 4 * q) + r;
                    if (j < mb && (sarr[j] & 3) == 3) {
                        int b = prtok[base + j];
                        const float* st = &g_stage4[(size_t)b * 4 * D_DATA + d];
                        float s0 = __ldcg(st);
                        float s1 = __ldcg(st + D_DATA);
                        float s2 = __ldcg(st + 2 * D_DATA);
                        float s3 = __ldcg(st + 3 * D_DATA);
                        out[(size_t)b * D_DATA + d] = (s0 + s1) + (s2 + s3);
                    }
                }
            }
        }
        __syncthreads();   // before next batch reuses rings/xs/acts
    }
}

// ---------------------------------------------------------------------------
// Launch. Inputs (metadata order): x, gate, W_enc, W_dec, b_enc, b_dec, k
// ---------------------------------------------------------------------------
extern "C" void kernel_launch(void* const* d_in, const int* in_sizes, int n_in,
                              void* d_out, int out_size) {
    const float* x    = (const float*)d_in[0];
    const float* gate = (const float*)d_in[1];
    const float* Wenc = (const float*)d_in[2];
    const float* Wdec = (const float*)d_in[3];
    const float* benc = (const float*)d_in[4];
    const float* bdec = (const float*)d_in[5];
    float* out = (float*)d_out;

    cudaFuncSetAttribute(k_compute, cudaFuncAttributeMaxDynamicSharedMemorySize,
                         SMEM_BYTES);

    dim3 grid(N_SAE, 2);
    k_compute<<<grid, 512, SMEM_BYTES>>>(x, gate, Wenc, Wdec, benc, bdec, out);
}